// round 17
// baseline (speedup 1.0000x reference)
#include <cuda_runtime.h>
#include <cstdint>

#define NN 2048
#define TT 4096
#define MAXS 256
#define C_CTAS 8
#define NPC 256            /* neurons (=threads) per CTA */
#define WARPS 8            /* warps per CTA */
#define NSLOTS 64          /* total publishing warps in cluster */
#define DEPTH 8            /* slot ring depth (resolve lag is 2, lead <= 4) */
#define PF 8               /* ic/ur prefetch depth (register ring) */
#define DT 2.44140625e-4f  /* (1-0)/4096, exact in fp32 */
#define ALPHA_F 0.01f
#define FULLM 0xffffffffu

__global__ void init_kernel(float* __restrict__ out) {
    int idx = blockIdx.x * blockDim.x + threadIdx.x;
    int stride = gridDim.x * blockDim.x;
    // Output layout: [ys (T*N*3)] [tev (256)] [yev (256*N*3)] [et (256*N)] [num_spikes (1)]
    float* tev = out + (size_t)TT * NN * 3;
    const int inf_n = MAXS + MAXS * NN * 3;          // tevents + yevents -> +inf
    const float finf = __int_as_float(0x7f800000);
    for (int t = idx; t < inf_n; t += stride) tev[t] = finf;
    float* et = tev + inf_n;
    const int et_n = MAXS * NN;                      // event_types -> 0
    for (int t = idx; t < et_n; t += stride) et[t] = 0.0f;
}

__device__ __forceinline__ void ld_vol_shared_v2(unsigned addr, unsigned& a, unsigned& b) {
    asm volatile("ld.volatile.shared.v2.u32 {%0, %1}, [%2];"
                 : "=r"(a), "=r"(b) : "r"(addr));
}
__device__ __forceinline__ void st_shared_cluster(unsigned addr, unsigned v) {
    asm volatile("st.shared::cluster.u32 [%0], %1;" :: "r"(addr), "r"(v) : "memory");
}
__device__ __forceinline__ unsigned mapa_u32(unsigned addr, unsigned rank) {
    unsigned r;
    asm("mapa.shared::cluster.u32 %0, %1, %2;" : "=r"(r) : "r"(addr), "r"(rank));
    return r;
}
__device__ __forceinline__ unsigned smem_u32(const void* p) {
    unsigned a;
    asm("{ .reg .u64 t; cvta.to.shared.u64 t, %1; cvt.u32.u64 %0, t; }" : "=r"(a) : "l"(p));
    return a;
}

// Exact jax.nn.softplus(x) = max(x,0) + log1p(exp(-|x|))
__device__ __forceinline__ float softplus_ref(float v) {
    float ax = fabsf(v);
    float e  = expf(-ax);
    float l  = log1pf(e);
    return __fadd_rn(fmaxf(v, 0.0f), l);
}

__global__ void __launch_bounds__(NPC, 1) __cluster_dims__(C_CTAS, 1, 1)
sim_kernel(const float* __restrict__ w,  const float* __restrict__ mu,
           const float* __restrict__ v0, const float* __restrict__ i0,
           const float* __restrict__ ic, const float* __restrict__ u0,
           const float* __restrict__ ur, float* __restrict__ out)
{
    __shared__ __align__(16) unsigned slots[DEPTH * NSLOTS];  // [ring][64 warp slots]

    const int t    = threadIdx.x;
    const int lane = t & 31;
    const int wid  = t >> 5;
    const int cta  = blockIdx.x;                 // grid == one cluster -> rank
    const int n    = cta * NPC + t;

    const float mu1  = mu[0];
    const float nmu2 = -mu[1];
    const float dt   = DT;

    float* ys  = out;
    float* tev = out + (size_t)TT * NN * 3;
    float* yev = tev + MAXS;
    float* et  = yev + (size_t)MAXS * NN * 3;
    float* nsp = et  + (size_t)MAXS * NN;

    // zero the slot ring, then cluster-sync before anyone publishes
    for (int i = t; i < DEPTH * NSLOTS; i += NPC) slots[i] = 0u;
    const unsigned sbase = smem_u32(slots);
    // each of lanes 0..7 injects the publish into one peer CTA
    const unsigned my_peer = mapa_u32(sbase, (unsigned)(lane & 7));
    const unsigned my_slot_off = (unsigned)(cta * WARPS + wid) * 4u;
    const unsigned base_code = (unsigned)(cta * NPC + wid * 32);
    asm volatile("barrier.cluster.arrive.aligned;" ::: "memory");
    asm volatile("barrier.cluster.wait.aligned;"   ::: "memory");

    // prefetch ring: ic/u for steps 0..PF-1
    float icb[PF], ub[PF];
    #pragma unroll
    for (int j = 0; j < PF; ++j) {
        icb[j] = __ldg(&ic[(size_t)j * NN + n]);
        ub[j]  = __ldg(&ur[(size_t)j * NN + n]);
    }

    const float i0v = i0[n];
    int cnt = 0;

    // ---- carries (set by prologue), entering iter k:
    // vA,sA   : v2(k-2), s2(k-2)
    // iP      : i1(k-2) (decayed, pre-w-row)
    // v1A,s1A,maskA : v1,s1,mask of step k-2 (event outputs)
    // maskC,s1C     : mask,s1 of step k-1 (from publish(k-1))
    float vA, sA, iP, v1A, s1A, s1C;
    bool  maskA, maskC;

    // ---------------- prologue: steps 0 and 1 (no polls needed) ----------------
    {
        float v00 = v0[n];
        float s00 = __fsub_rn(logf(u0[n]), ALPHA_F);

        // publish(0)
        float sp0 = softplus_ref(v00);
        float s1_0 = __fadd_rn(s00, __fmul_rn(dt, sp0));
        bool  mask0 = (s1_0 >= 0.0f);
        unsigned bal0  = __ballot_sync(FULLM, mask0);
        unsigned code0 = bal0 ? base_code + (unsigned)__ffs(bal0) : 0xFFFu;
        if (lane < 8) st_shared_cluster(my_peer + my_slot_off, (1u << 12) | code0);

        // advance step 0 (i2(-1) = i0)
        float ick0 = icb[0];
        float lu0  = __fsub_rn(logf(ub[0]), ALPHA_F);
        icb[0] = __ldg(&ic[(size_t)PF * NN + n]);
        ub[0]  = __ldg(&ur[(size_t)PF * NN + n]);

        float t1  = __fsub_rn(__fadd_rn(i0v, ick0), v00);
        float v1_0 = __fadd_rn(v00, __fmul_rn(dt, __fmul_rn(mu1, t1)));
        float i1_0 = __fadd_rn(i0v, __fmul_rn(dt, __fmul_rn(nmu2, i0v)));
        float v2_0 = mask0 ? __fsub_rn(v1_0, 1.0f) : v1_0;
        float s2_0 = mask0 ? lu0 : s1_0;

        // publish(1)
        float sp1 = softplus_ref(v2_0);
        float s1_1 = __fadd_rn(s2_0, __fmul_rn(dt, sp1));
        bool  mask1 = (s1_1 >= 0.0f);
        unsigned bal1  = __ballot_sync(FULLM, mask1);
        unsigned code1 = bal1 ? base_code + (unsigned)__ffs(bal1) : 0xFFFu;
        if (lane < 8)
            st_shared_cluster(my_peer + (unsigned)(1 * NSLOTS) * 4u + my_slot_off,
                              (2u << 12) | code1);

        vA = v2_0; sA = s2_0; iP = i1_0;
        v1A = v1_0; s1A = s1_0; maskA = mask0;
        maskC = mask1; s1C = s1_1;
    }

    // ---------------- main loop k = 2 .. TT-1 ----------------
    // iter k: resolve(k-2) -> outputs(k-2) -> advance(k-1) -> publish(k)
    #pragma unroll 16
    for (int k = 2; k < TT; ++k) {
        // ---- 1. poll(k-2): published two iterations ago -> vis amortized ----
        const unsigned want = (unsigned)(k - 1) << 12;     // tag of step k-2
        const unsigned boff = sbase + (unsigned)(((k - 2) & (DEPTH - 1)) * NSLOTS) * 4u
                                    + (unsigned)lane * 8u;
        unsigned a, b;
        do { ld_vol_shared_v2(boff, a, b); }
        while (__ballot_sync(FULLM, (((a ^ want) | (b ^ want)) & 0xFFFFF000u) != 0u));
        unsigned m = __reduce_min_sync(FULLM, umin(a, b));
        unsigned ecode = m & 0xFFFu;
        bool eventp = (ecode != 0xFFFu);
        unsigned row = eventp ? (ecode - 1u) : 0u;         // unconditional, row 0 L1-hot
        float wraw = __ldg(&w[(size_t)row * NN + n]);
        float wv   = eventp ? wraw : 0.0f;

        // ---- 2. finish step k-2 ----
        float i2 = __fadd_rn(iP, wv);                      // +0 exact when no event
        size_t ob = ((size_t)(k - 2) * NN + n) * 3;
        ys[ob + 0] = vA;
        ys[ob + 1] = i2;
        ys[ob + 2] = sA;
        if (eventp && cnt < MAXS) {
            size_t eb = ((size_t)cnt * NN + n) * 3;
            yev[eb + 0] = v1A;                             // pre-transition y at step k-2
            yev[eb + 1] = iP;
            yev[eb + 2] = s1A;
            et[(size_t)cnt * NN + n] = maskA ? 1.0f : 0.0f;
            if (n == 0) tev[cnt] = __fmul_rn((float)(k - 1), dt);  // ((k-2)+1)*dt
            cnt++;
        }

        // ---- 3. advance step k-1 (inputs consumed from ring) ----
        const int p = (k - 1) & (PF - 1);
        float ick = icb[p];
        float lu  = __fsub_rn(logf(ub[p]), ALPHA_F);
        int   kp  = (k - 1 + PF < TT) ? (k - 1 + PF) : (TT - 1);
        icb[p] = __ldg(&ic[(size_t)kp * NN + n]);
        ub[p]  = __ldg(&ur[(size_t)kp * NN + n]);

        float t1  = __fsub_rn(__fadd_rn(i2, ick), vA);
        float v1B = __fadd_rn(vA, __fmul_rn(dt, __fmul_rn(mu1, t1)));
        float i1B = __fadd_rn(i2, __fmul_rn(dt, __fmul_rn(nmu2, i2)));
        float v2B = maskC ? __fsub_rn(v1B, 1.0f) : v1B;
        float s2B = maskC ? lu : s1C;

        // ---- 4. publish(k) ----
        float sp = softplus_ref(v2B);
        float s1k = __fadd_rn(s2B, __fmul_rn(dt, sp));
        bool  maskk = (s1k >= 0.0f);
        unsigned bal  = __ballot_sync(FULLM, maskk);
        unsigned code = bal ? base_code + (unsigned)__ffs(bal) : 0xFFFu;
        unsigned val  = ((unsigned)(k + 1) << 12) | code;
        if (lane < 8)
            st_shared_cluster(my_peer + (unsigned)((k & (DEPTH - 1)) * NSLOTS) * 4u
                                      + my_slot_off, val);

        // ---- 5. rotate carries ----
        v1A = v1B; s1A = s1C; maskA = maskC;               // step k-1 event package
        vA = v2B; sA = s2B; iP = i1B;                      // state of step k-1
        maskC = maskk; s1C = s1k;                          // decision of step k
    }

    // ---------------- epilogue A: resolve step TT-2, advance step TT-1 ----------------
    float v1B, i1B, v2B, s2B;
    {
        const unsigned want = (unsigned)(TT - 1) << 12;
        const unsigned boff = sbase + (unsigned)(((TT - 2) & (DEPTH - 1)) * NSLOTS) * 4u
                                    + (unsigned)lane * 8u;
        unsigned a, b;
        do { ld_vol_shared_v2(boff, a, b); }
        while (__ballot_sync(FULLM, (((a ^ want) | (b ^ want)) & 0xFFFFF000u) != 0u));
        unsigned m = __reduce_min_sync(FULLM, umin(a, b));
        unsigned ecode = m & 0xFFFu;
        bool eventp = (ecode != 0xFFFu);
        float wv = 0.0f;
        if (eventp) wv = __ldg(&w[(size_t)(ecode - 1u) * NN + n]);

        float i2 = __fadd_rn(iP, wv);
        size_t ob = ((size_t)(TT - 2) * NN + n) * 3;
        ys[ob + 0] = vA;
        ys[ob + 1] = i2;
        ys[ob + 2] = sA;
        if (eventp && cnt < MAXS) {
            size_t eb = ((size_t)cnt * NN + n) * 3;
            yev[eb + 0] = v1A;
            yev[eb + 1] = iP;
            yev[eb + 2] = s1A;
            et[(size_t)cnt * NN + n] = maskA ? 1.0f : 0.0f;
            if (n == 0) tev[cnt] = __fmul_rn((float)(TT - 1), dt);
            cnt++;
        }

        const int p = (TT - 1) & (PF - 1);
        float ick = icb[p];
        float lu  = __fsub_rn(logf(ub[p]), ALPHA_F);
        float t1  = __fsub_rn(__fadd_rn(i2, ick), vA);
        v1B = __fadd_rn(vA, __fmul_rn(dt, __fmul_rn(mu1, t1)));
        i1B = __fadd_rn(i2, __fmul_rn(dt, __fmul_rn(nmu2, i2)));
        v2B = maskC ? __fsub_rn(v1B, 1.0f) : v1B;
        s2B = maskC ? lu : s1C;
    }

    // ---------------- epilogue B: resolve step TT-1 ----------------
    {
        const unsigned want = (unsigned)TT << 12;
        const unsigned boff = sbase + (unsigned)(((TT - 1) & (DEPTH - 1)) * NSLOTS) * 4u
                                    + (unsigned)lane * 8u;
        unsigned a, b;
        do { ld_vol_shared_v2(boff, a, b); }
        while (__ballot_sync(FULLM, (((a ^ want) | (b ^ want)) & 0xFFFFF000u) != 0u));
        unsigned m = __reduce_min_sync(FULLM, umin(a, b));
        unsigned ecode = m & 0xFFFu;
        bool eventp = (ecode != 0xFFFu);
        float wv = 0.0f;
        if (eventp) wv = __ldg(&w[(size_t)(ecode - 1u) * NN + n]);
        float i2 = __fadd_rn(i1B, wv);

        size_t ob = ((size_t)(TT - 1) * NN + n) * 3;
        ys[ob + 0] = v2B;
        ys[ob + 1] = i2;
        ys[ob + 2] = s2B;
        if (eventp && cnt < MAXS) {
            size_t eb = ((size_t)cnt * NN + n) * 3;
            yev[eb + 0] = v1B;
            yev[eb + 1] = i1B;
            yev[eb + 2] = s1C;
            et[(size_t)cnt * NN + n] = maskC ? 1.0f : 0.0f;
            if (n == 0) tev[cnt] = __fmul_rn((float)TT, dt);
            cnt++;
        }
    }

    if (n == 0) nsp[0] = (float)cnt;

    // no CTA may exit while peers could still address its SMEM
    asm volatile("barrier.cluster.arrive.aligned;" ::: "memory");
    asm volatile("barrier.cluster.wait.aligned;"   ::: "memory");
}

extern "C" void kernel_launch(void* const* d_in, const int* in_sizes, int n_in,
                              void* d_out, int out_size) {
    const float* w  = (const float*)d_in[0];
    const float* mu = (const float*)d_in[1];
    const float* v0 = (const float*)d_in[2];
    const float* i0 = (const float*)d_in[3];
    const float* ic = (const float*)d_in[4];
    const float* u0 = (const float*)d_in[5];
    const float* ur = (const float*)d_in[6];
    float* out = (float*)d_out;

    init_kernel<<<512, 256>>>(out);
    sim_kernel<<<C_CTAS, NPC>>>(w, mu, v0, i0, ic, u0, ur, out);
    (void)in_sizes; (void)n_in; (void)out_size;
}